// round 3
// baseline (speedup 1.0000x reference)
#include <cuda_runtime.h>
#include <cuda_bf16.h>

#define NB 8
#define NN 2048
#define NTHREADS 256
#define CHUNKS_PER_THREAD (NN / 4 / NTHREADS)   // 2

__global__ __launch_bounds__(NTHREADS) void gauss_adj_row_kernel(
    const float* __restrict__ coords,    // [B, N, 3]
    const float4* __restrict__ masks,    // [B, N, N] viewed as float4
    const float* __restrict__ sigma,     // [1]
    float4* __restrict__ out)            // [B, N, N] viewed as float4
{
    // Per-batch coordinates staged as (x, y, z, |x|^2): 2048 * 16B = 32 KB
    __shared__ float4 sc[NN];
    __shared__ float wsum[NTHREADS / 32];

    const int row = blockIdx.x;            // 0 .. B*N-1
    const int b   = row >> 11;             // row / N
    const int i   = row & (NN - 1);        // row % N
    const int tid = threadIdx.x;

    const float* cb = coords + (size_t)b * NN * 3;

    // Stage coordinates + precomputed squared norms
    for (int j = tid; j < NN; j += NTHREADS) {
        float x = cb[3 * j + 0];
        float y = cb[3 * j + 1];
        float z = cb[3 * j + 2];
        sc[j] = make_float4(x, y, z, x * x + y * y + z * z);
    }
    __syncthreads();

    const float4 ci = sc[i];
    const float  ni = ci.w;
    const float  s  = sigma[0];
    const float  neg_inv_s2 = -1.0f / (s * s);

    const float4* mrow = masks + (size_t)row * (NN / 4);
    float4*       orow = out   + (size_t)row * (NN / 4);

    // Compute masked Gaussian values; keep them in registers.
    float4 acc[CHUNKS_PER_THREAD];
    float  sum = 0.0f;

    #pragma unroll
    for (int c = 0; c < CHUNKS_PER_THREAD; c++) {
        const int j4 = tid + c * NTHREADS;     // float4 index within row
        const int j  = j4 << 2;
        const float4 m = mrow[j4];             // single mask read (HBM stream)

        float4 p0 = sc[j + 0];
        float4 p1 = sc[j + 1];
        float4 p2 = sc[j + 2];
        float4 p3 = sc[j + 3];

        float d0 = ni - 2.0f * (ci.x * p0.x + ci.y * p0.y + ci.z * p0.z) + p0.w;
        float d1 = ni - 2.0f * (ci.x * p1.x + ci.y * p1.y + ci.z * p1.z) + p1.w;
        float d2 = ni - 2.0f * (ci.x * p2.x + ci.y * p2.y + ci.z * p2.z) + p2.w;
        float d3 = ni - 2.0f * (ci.x * p3.x + ci.y * p3.y + ci.z * p3.z) + p3.w;

        float4 a;
        a.x = __expf(d0 * neg_inv_s2) * m.x;
        a.y = __expf(d1 * neg_inv_s2) * m.y;
        a.z = __expf(d2 * neg_inv_s2) * m.z;
        a.w = __expf(d3 * neg_inv_s2) * m.w;

        acc[c] = a;
        sum += (a.x + a.y) + (a.z + a.w);
    }

    // Row-sum reduction: intra-warp shuffle, then across the 8 warps.
    #pragma unroll
    for (int off = 16; off > 0; off >>= 1)
        sum += __shfl_down_sync(0xffffffffu, sum, off);

    const int lane = tid & 31;
    const int wid  = tid >> 5;
    if (lane == 0) wsum[wid] = sum;
    __syncthreads();

    float total = 0.0f;
    #pragma unroll
    for (int k = 0; k < NTHREADS / 32; k++) total += wsum[k];

    const float inv = 1.0f / (total + 1e-8f);

    // Normalize from registers and stream out.
    #pragma unroll
    for (int c = 0; c < CHUNKS_PER_THREAD; c++) {
        const int j4 = tid + c * NTHREADS;
        float4 a = acc[c];
        orow[j4] = make_float4(a.x * inv, a.y * inv, a.z * inv, a.w * inv);
    }
}

extern "C" void kernel_launch(void* const* d_in, const int* in_sizes, int n_in,
                              void* d_out, int out_size)
{
    const float*  coords = (const float*)d_in[0];   // [8,2048,3]
    const float4* masks  = (const float4*)d_in[1];  // [8,2048,2048]
    const float*  sigma  = (const float*)d_in[2];   // [1]
    float4*       out    = (float4*)d_out;          // [8,2048,2048]

    (void)in_sizes; (void)n_in; (void)out_size;

    dim3 grid(NB * NN);
    dim3 block(NTHREADS);
    gauss_adj_row_kernel<<<grid, block>>>(coords, masks, sigma, out);
}

// round 4
// speedup vs baseline: 1.4078x; 1.4078x over previous
#include <cuda_runtime.h>
#include <cuda_bf16.h>

#define NB 8
#define NN 2048
#define NTHREADS 256
#define CHUNKS_PER_THREAD (NN / 4 / NTHREADS)   // 2

// Bank-conflict-free float4 smem swizzle for the access pattern j = 4*tid + k.
__device__ __forceinline__ int swz(int j) { return j ^ ((j >> 3) & 7); }

__global__ __launch_bounds__(NTHREADS) void gauss_adj_row_kernel(
    const float* __restrict__ coords,    // [B, N, 3]
    const float4* __restrict__ masks,    // [B, N, N] viewed as float4
    const float* __restrict__ sigma,     // [1]
    float4* __restrict__ out)            // [B, N, N] viewed as float4
{
    // Per-batch coordinates staged as (x, y, z, |x|^2), XOR-swizzled: 32 KB
    __shared__ float4 sc[NN];
    __shared__ float wsum[NTHREADS / 32];

    const int row = blockIdx.x;            // 0 .. B*N-1
    const int b   = row >> 11;             // row / N
    const int i   = row & (NN - 1);        // row % N
    const int tid = threadIdx.x;

    const float* cb = coords + (size_t)b * NN * 3;

    // Stage coordinates + precomputed squared norms (swizzled store)
    for (int j = tid; j < NN; j += NTHREADS) {
        float x = cb[3 * j + 0];
        float y = cb[3 * j + 1];
        float z = cb[3 * j + 2];
        sc[swz(j)] = make_float4(x, y, z, x * x + y * y + z * z);
    }
    __syncthreads();

    const float4 ci = sc[swz(i)];
    const float  ni = ci.w;
    const float  s  = sigma[0];
    const float  neg_inv_s2 = -1.0f / (s * s);

    const float4* mrow = masks + (size_t)row * (NN / 4);
    float4*       orow = out   + (size_t)row * (NN / 4);

    // Compute masked Gaussian values; keep them in registers.
    float4 acc[CHUNKS_PER_THREAD];
    float  sum = 0.0f;

    #pragma unroll
    for (int c = 0; c < CHUNKS_PER_THREAD; c++) {
        const int j4 = tid + c * NTHREADS;     // float4 index within row
        const int j  = j4 << 2;
        const float4 m = mrow[j4];             // single mask read (HBM stream)

        // XOR term is constant across the thread's 4 consecutive indices
        // (j is a multiple of 4, so j..j+3 share the same (>>3) group).
        const int x7 = (j >> 3) & 7;
        float4 p0 = sc[(j + 0) ^ x7];
        float4 p1 = sc[(j + 1) ^ x7];
        float4 p2 = sc[(j + 2) ^ x7];
        float4 p3 = sc[(j + 3) ^ x7];

        float d0 = ni - 2.0f * (ci.x * p0.x + ci.y * p0.y + ci.z * p0.z) + p0.w;
        float d1 = ni - 2.0f * (ci.x * p1.x + ci.y * p1.y + ci.z * p1.z) + p1.w;
        float d2 = ni - 2.0f * (ci.x * p2.x + ci.y * p2.y + ci.z * p2.z) + p2.w;
        float d3 = ni - 2.0f * (ci.x * p3.x + ci.y * p3.y + ci.z * p3.z) + p3.w;

        float4 a;
        // Note: swizzle permutes which column each pk corresponds to.
        // (j+k)^x7 is the STORAGE index; the logical column of pk is (j+k)
        // only if load index == swz(logical). We loaded storage (j+k)^x7,
        // which holds logical column swz_inv((j+k)^x7). swz is an involution
        // on its own image here? Careful: we must load logical columns
        // j..j+3. Logical column q lives at storage swz(q) = q ^ ((q>>3)&7).
        // For q = j+k (same >>3 group), swz(q) = (j+k) ^ x7. So pk IS logical
        // column j+k. Correct as written.
        a.x = __expf(d0 * neg_inv_s2) * m.x;
        a.y = __expf(d1 * neg_inv_s2) * m.y;
        a.z = __expf(d2 * neg_inv_s2) * m.z;
        a.w = __expf(d3 * neg_inv_s2) * m.w;

        acc[c] = a;
        sum += (a.x + a.y) + (a.z + a.w);
    }

    // Row-sum reduction: intra-warp shuffle, then across the 8 warps.
    #pragma unroll
    for (int off = 16; off > 0; off >>= 1)
        sum += __shfl_down_sync(0xffffffffu, sum, off);

    const int lane = tid & 31;
    const int wid  = tid >> 5;
    if (lane == 0) wsum[wid] = sum;
    __syncthreads();

    float total = 0.0f;
    #pragma unroll
    for (int k = 0; k < NTHREADS / 32; k++) total += wsum[k];

    const float inv = 1.0f / (total + 1e-8f);

    // Normalize from registers and stream out.
    #pragma unroll
    for (int c = 0; c < CHUNKS_PER_THREAD; c++) {
        const int j4 = tid + c * NTHREADS;
        float4 a = acc[c];
        orow[j4] = make_float4(a.x * inv, a.y * inv, a.z * inv, a.w * inv);
    }
}

extern "C" void kernel_launch(void* const* d_in, const int* in_sizes, int n_in,
                              void* d_out, int out_size)
{
    const float*  coords = (const float*)d_in[0];   // [8,2048,3]
    const float4* masks  = (const float4*)d_in[1];  // [8,2048,2048]
    const float*  sigma  = (const float*)d_in[2];   // [1]
    float4*       out    = (float4*)d_out;          // [8,2048,2048]

    (void)in_sizes; (void)n_in; (void)out_size;

    dim3 grid(NB * NN);
    dim3 block(NTHREADS);
    gauss_adj_row_kernel<<<grid, block>>>(coords, masks, sigma, out);
}

// round 7
// speedup vs baseline: 2.3176x; 1.6463x over previous
#include <cuda_runtime.h>
#include <cuda_bf16.h>

#define NB 8
#define NN 2048
#define NTHREADS 256
#define RPB 8                         // rows per block (same batch: 2048 % 8 == 0)
#define NWARPS (NTHREADS / 32)

// Load 4 consecutive columns' coordinates (12 floats, 16B-aligned) into
// (x, y, z, |x|^2) register lanes.
__device__ __forceinline__ void load_cols4(const float* __restrict__ cb,
                                           int col0, float4 p[4])
{
    const float4* f = reinterpret_cast<const float4*>(cb + 3 * col0);
    float4 f0 = f[0], f1 = f[1], f2 = f[2];
    p[0] = make_float4(f0.x, f0.y, f0.z, f0.x*f0.x + f0.y*f0.y + f0.z*f0.z);
    p[1] = make_float4(f0.w, f1.x, f1.y, f0.w*f0.w + f1.x*f1.x + f1.y*f1.y);
    p[2] = make_float4(f1.z, f1.w, f2.x, f1.z*f1.z + f1.w*f1.w + f2.x*f2.x);
    p[3] = make_float4(f2.y, f2.z, f2.w, f2.y*f2.y + f2.z*f2.z + f2.w*f2.w);
}

// Masked Gaussian for 4 columns held in registers.
__device__ __forceinline__ float4 gauss4(float4 ci, const float4 p[4],
                                         float4 m, float nis2)
{
    float d0 = ci.w - 2.0f * (ci.x*p[0].x + ci.y*p[0].y + ci.z*p[0].z) + p[0].w;
    float d1 = ci.w - 2.0f * (ci.x*p[1].x + ci.y*p[1].y + ci.z*p[1].z) + p[1].w;
    float d2 = ci.w - 2.0f * (ci.x*p[2].x + ci.y*p[2].y + ci.z*p[2].z) + p[2].w;
    float d3 = ci.w - 2.0f * (ci.x*p[3].x + ci.y*p[3].y + ci.z*p[3].z) + p[3].w;
    float4 a;
    a.x = __expf(d0 * nis2) * m.x;
    a.y = __expf(d1 * nis2) * m.y;
    a.z = __expf(d2 * nis2) * m.z;
    a.w = __expf(d3 * nis2) * m.w;
    return a;
}

__global__ __launch_bounds__(NTHREADS) void gauss_adj_kernel(
    const float* __restrict__ coords,    // [B, N, 3]
    const float4* __restrict__ masks,    // [B, N, N] as float4
    const float* __restrict__ sigma,     // [1]
    float4* __restrict__ out)            // [B, N, N] as float4
{
    __shared__ float4 sci[RPB];          // query coords for this block's rows
    __shared__ float  wsum[2][NWARPS];   // double-buffered cross-warp partials

    const int tid  = threadIdx.x;
    const int lane = tid & 31;
    const int wid  = tid >> 5;

    const int row0 = blockIdx.x * RPB;   // first row of this block
    const int b    = row0 >> 11;         // batch index (row0 / N)
    const float* cb = coords + (size_t)b * NN * 3;

    // Per-thread column coordinates, resident in registers for all RPB rows.
    float4 pA[4], pB[4];
    load_cols4(cb, 4 * tid,              pA);
    load_cols4(cb, 4 * (tid + NTHREADS), pB);

    // Stage the RPB query-point coords (+norms).
    if (tid < RPB) {
        int i = (row0 + tid) & (NN - 1);
        float x = cb[3*i], y = cb[3*i + 1], z = cb[3*i + 2];
        sci[tid] = make_float4(x, y, z, x*x + y*y + z*z);
    }
    __syncthreads();

    const float s    = sigma[0];
    const float nis2 = -1.0f / (s * s);

    #pragma unroll
    for (int r = 0; r < RPB; r++) {
        const size_t row = (size_t)row0 + r;
        const float4* mrow = masks + row * (NN / 4);
        float4*       orow = out   + row * (NN / 4);
        const float4 ci = sci[r];

        // Mask loads first (front-batched for MLP), then compute.
        float4 mA = mrow[tid];
        float4 mB = mrow[tid + NTHREADS];

        float4 aA = gauss4(ci, pA, mA, nis2);
        float4 aB = gauss4(ci, pB, mB, nis2);

        float sum = (aA.x + aA.y) + (aA.z + aA.w)
                  + (aB.x + aB.y) + (aB.z + aB.w);

        #pragma unroll
        for (int off = 16; off > 0; off >>= 1)
            sum += __shfl_down_sync(0xffffffffu, sum, off);

        if (lane == 0) wsum[r & 1][wid] = sum;
        __syncthreads();

        float total = 0.0f;
        #pragma unroll
        for (int k = 0; k < NWARPS; k++) total += wsum[r & 1][k];

        const float inv = 1.0f / (total + 1e-8f);

        orow[tid]            = make_float4(aA.x*inv, aA.y*inv, aA.z*inv, aA.w*inv);
        orow[tid + NTHREADS] = make_float4(aB.x*inv, aB.y*inv, aB.z*inv, aB.w*inv);
        // No trailing barrier needed: buffer r&1 is only rewritten at r+2,
        // and the r+1 barrier separates any straggler reads from that write.
    }
}

extern "C" void kernel_launch(void* const* d_in, const int* in_sizes, int n_in,
                              void* d_out, int out_size)
{
    const float*  coords = (const float*)d_in[0];   // [8,2048,3]
    const float4* masks  = (const float4*)d_in[1];  // [8,2048,2048]
    const float*  sigma  = (const float*)d_in[2];   // [1]
    float4*       out    = (float4*)d_out;          // [8,2048,2048]

    (void)in_sizes; (void)n_in; (void)out_size;

    dim3 grid(NB * NN / RPB);   // 2048 blocks
    dim3 block(NTHREADS);
    gauss_adj_kernel<<<grid, block>>>(coords, masks, sigma, out);
}

// round 9
// speedup vs baseline: 2.4669x; 1.0644x over previous
#include <cuda_runtime.h>
#include <cuda_bf16.h>

#define NB 8
#define NN 2048
#define NTHREADS 256
#define RPB 8                         // rows per block (same batch: 2048 % 8 == 0)
#define NWARPS (NTHREADS / 32)

// Load 4 consecutive columns' coordinates (12 floats, 16B-aligned) into
// (x, y, z, |x|^2) register lanes.
__device__ __forceinline__ void load_cols4(const float* __restrict__ cb,
                                           int col0, float4 p[4])
{
    const float4* f = reinterpret_cast<const float4*>(cb + 3 * col0);
    float4 f0 = f[0], f1 = f[1], f2 = f[2];
    p[0] = make_float4(f0.x, f0.y, f0.z, f0.x*f0.x + f0.y*f0.y + f0.z*f0.z);
    p[1] = make_float4(f0.w, f1.x, f1.y, f0.w*f0.w + f1.x*f1.x + f1.y*f1.y);
    p[2] = make_float4(f1.z, f1.w, f2.x, f1.z*f1.z + f1.w*f1.w + f2.x*f2.x);
    p[3] = make_float4(f2.y, f2.z, f2.w, f2.y*f2.y + f2.z*f2.z + f2.w*f2.w);
}

// Masked Gaussian for 4 columns held in registers.
__device__ __forceinline__ float4 gauss4(float4 ci, const float4 p[4],
                                         float4 m, float nis2)
{
    float d0 = ci.w - 2.0f * (ci.x*p[0].x + ci.y*p[0].y + ci.z*p[0].z) + p[0].w;
    float d1 = ci.w - 2.0f * (ci.x*p[1].x + ci.y*p[1].y + ci.z*p[1].z) + p[1].w;
    float d2 = ci.w - 2.0f * (ci.x*p[2].x + ci.y*p[2].y + ci.z*p[2].z) + p[2].w;
    float d3 = ci.w - 2.0f * (ci.x*p[3].x + ci.y*p[3].y + ci.z*p[3].z) + p[3].w;
    float4 a;
    a.x = __expf(d0 * nis2) * m.x;
    a.y = __expf(d1 * nis2) * m.y;
    a.z = __expf(d2 * nis2) * m.z;
    a.w = __expf(d3 * nis2) * m.w;
    return a;
}

__global__ __launch_bounds__(NTHREADS, 3) void gauss_adj_kernel(
    const float* __restrict__ coords,    // [B, N, 3]
    const float4* __restrict__ masks,    // [B, N, N] as float4
    const float* __restrict__ sigma,     // [1]
    float4* __restrict__ out)            // [B, N, N] as float4
{
    __shared__ float4 sci[RPB];          // query coords for this block's rows
    __shared__ float  wsum[2][NWARPS];   // double-buffered cross-warp partials

    const int tid  = threadIdx.x;
    const int lane = tid & 31;
    const int wid  = tid >> 5;

    const int row0 = blockIdx.x * RPB;   // first row of this block
    const int b    = row0 >> 11;         // batch index (row0 / N)
    const float* cb = coords + (size_t)b * NN * 3;

    const float4* mptr = masks + (size_t)row0 * (NN / 4);
    float4*       optr = out   + (size_t)row0 * (NN / 4);

    // Kick off row 0's mask loads before anything else (hide behind prologue).
    float4 mA = __ldcs(mptr + tid);
    float4 mB = __ldcs(mptr + tid + NTHREADS);

    // Per-thread column coordinates, resident in registers for all RPB rows.
    float4 pA[4], pB[4];
    load_cols4(cb, 4 * tid,              pA);
    load_cols4(cb, 4 * (tid + NTHREADS), pB);

    // Stage the RPB query-point coords (+norms).
    if (tid < RPB) {
        int i = (row0 + tid) & (NN - 1);
        float x = cb[3*i], y = cb[3*i + 1], z = cb[3*i + 2];
        sci[tid] = make_float4(x, y, z, x*x + y*y + z*z);
    }
    __syncthreads();

    const float s    = sigma[0];
    const float nis2 = -1.0f / (s * s);

    #pragma unroll
    for (int r = 0; r < RPB; r++) {
        // Prefetch next row's masks BEFORE this row's compute/reduce/barrier,
        // so the DRAM stream overlaps the whole per-row critical path.
        float4 nA = make_float4(0.f, 0.f, 0.f, 0.f);
        float4 nB = nA;
        if (r + 1 < RPB) {
            const float4* mnext = mptr + (size_t)(r + 1) * (NN / 4);
            nA = __ldcs(mnext + tid);
            nB = __ldcs(mnext + tid + NTHREADS);
        }

        const float4 ci = sci[r];
        float4 aA = gauss4(ci, pA, mA, nis2);
        float4 aB = gauss4(ci, pB, mB, nis2);

        float sum = (aA.x + aA.y) + (aA.z + aA.w)
                  + (aB.x + aB.y) + (aB.z + aB.w);

        #pragma unroll
        for (int off = 16; off > 0; off >>= 1)
            sum += __shfl_down_sync(0xffffffffu, sum, off);

        if (lane == 0) wsum[r & 1][wid] = sum;
        __syncthreads();

        float total = 0.0f;
        #pragma unroll
        for (int k = 0; k < NWARPS; k++) total += wsum[r & 1][k];

        const float inv = 1.0f / (total + 1e-8f);

        float4* orow = optr + (size_t)r * (NN / 4);
        __stcs(orow + tid,            make_float4(aA.x*inv, aA.y*inv, aA.z*inv, aA.w*inv));
        __stcs(orow + tid + NTHREADS, make_float4(aB.x*inv, aB.y*inv, aB.z*inv, aB.w*inv));

        mA = nA;
        mB = nB;
        // No trailing barrier needed: buffer r&1 is only rewritten at r+2,
        // and the r+1 barrier separates any straggler reads from that write.
    }
}

extern "C" void kernel_launch(void* const* d_in, const int* in_sizes, int n_in,
                              void* d_out, int out_size)
{
    const float*  coords = (const float*)d_in[0];   // [8,2048,3]
    const float4* masks  = (const float4*)d_in[1];  // [8,2048,2048]
    const float*  sigma  = (const float*)d_in[2];   // [1]
    float4*       out    = (float4*)d_out;          // [8,2048,2048]

    (void)in_sizes; (void)n_in; (void)out_size;

    dim3 grid(NB * NN / RPB);   // 2048 blocks
    dim3 block(NTHREADS);
    gauss_adj_kernel<<<grid, block>>>(coords, masks, sigma, out);
}

// round 10
// speedup vs baseline: 2.5887x; 1.0494x over previous
#include <cuda_runtime.h>
#include <cuda_bf16.h>

#define NB 8
#define NN 2048
#define NTHREADS 256
#define RPB 8                         // rows per block (same batch: 2048 % 8 == 0)
#define NWARPS (NTHREADS / 32)

struct P3 { float x, y, z; };

// Load 4 consecutive columns' coordinates (12 floats, 16B-aligned), pre-scaled.
__device__ __forceinline__ void load_cols4(const float* __restrict__ cb,
                                           int col0, float sc, P3 p[4])
{
    const float4* f = reinterpret_cast<const float4*>(cb + 3 * col0);
    float4 f0 = f[0], f1 = f[1], f2 = f[2];
    p[0] = { f0.x * sc, f0.y * sc, f0.z * sc };
    p[1] = { f0.w * sc, f1.x * sc, f1.y * sc };
    p[2] = { f1.z * sc, f1.w * sc, f2.x * sc };
    p[3] = { f2.y * sc, f2.z * sc, f2.w * sc };
}

// Masked Gaussian for 4 columns (coords pre-scaled by sqrt(log2e)/sigma):
// a = exp2(-(dx^2+dy^2+dz^2)) * m  ==  exp(-d/sigma^2) * m
__device__ __forceinline__ float4 gauss4(P3 ci, const P3 p[4], float4 m)
{
    float4 a;
    #pragma unroll
    for (int k = 0; k < 4; k++) {
        float dx = ci.x - p[k].x;
        float dy = ci.y - p[k].y;
        float dz = ci.z - p[k].z;
        float e  = __fmaf_rn(dx, -dx, __fmaf_rn(dy, -dy, -dz * dz));
        float v  = exp2f(e);
        (&a.x)[k] = v * (&m.x)[k];
    }
    return a;
}

__global__ __launch_bounds__(NTHREADS, 4) void gauss_adj_kernel(
    const float* __restrict__ coords,    // [B, N, 3]
    const float4* __restrict__ masks,    // [B, N, N] as float4
    const float* __restrict__ sigma,     // [1]
    float4* __restrict__ out)            // [B, N, N] as float4
{
    __shared__ P3    sci[RPB];           // scaled query coords for block's rows
    __shared__ float wsum[2][NWARPS];    // double-buffered cross-warp partials

    const int tid  = threadIdx.x;
    const int lane = tid & 31;
    const int wid  = tid >> 5;

    const int row0 = blockIdx.x * RPB;   // first row of this block
    const int b    = row0 >> 11;         // batch index (row0 / N)
    const float* cb = coords + (size_t)b * NN * 3;

    const float4* mptr = masks + (size_t)row0 * (NN / 4);
    float4*       optr = out   + (size_t)row0 * (NN / 4);

    // Kick off row 0's mask loads before anything else.
    float4 mA = __ldcs(mptr + tid);
    float4 mB = __ldcs(mptr + tid + NTHREADS);

    // sqrt(log2(e)) / sigma — folds 1/sigma^2 and the exp->exp2 constant
    // into the coordinate pre-scale.
    const float s  = sigma[0];
    const float sc = __fsqrt_rn(1.4426950408889634f) / s;

    // Per-thread column coordinates (scaled), resident for all RPB rows.
    P3 pA[4], pB[4];
    load_cols4(cb, 4 * tid,              sc, pA);
    load_cols4(cb, 4 * (tid + NTHREADS), sc, pB);

    // Stage the RPB query-point coords (scaled).
    if (tid < RPB) {
        int i = (row0 + tid) & (NN - 1);
        sci[tid] = { cb[3*i] * sc, cb[3*i + 1] * sc, cb[3*i + 2] * sc };
    }
    __syncthreads();

    #pragma unroll
    for (int r = 0; r < RPB; r++) {
        // Prefetch next row's masks before this row's compute/reduce/barrier.
        float4 nA = make_float4(0.f, 0.f, 0.f, 0.f);
        float4 nB = nA;
        if (r + 1 < RPB) {
            const float4* mnext = mptr + (size_t)(r + 1) * (NN / 4);
            nA = __ldcs(mnext + tid);
            nB = __ldcs(mnext + tid + NTHREADS);
        }

        const P3 ci = sci[r];
        float4 aA = gauss4(ci, pA, mA);
        float4 aB = gauss4(ci, pB, mB);

        float sum = (aA.x + aA.y) + (aA.z + aA.w)
                  + (aB.x + aB.y) + (aB.z + aB.w);

        #pragma unroll
        for (int off = 16; off > 0; off >>= 1)
            sum += __shfl_down_sync(0xffffffffu, sum, off);

        if (lane == 0) wsum[r & 1][wid] = sum;
        __syncthreads();

        float total = 0.0f;
        #pragma unroll
        for (int k = 0; k < NWARPS; k++) total += wsum[r & 1][k];

        const float inv = 1.0f / (total + 1e-8f);

        float4* orow = optr + (size_t)r * (NN / 4);
        __stcs(orow + tid,            make_float4(aA.x*inv, aA.y*inv, aA.z*inv, aA.w*inv));
        __stcs(orow + tid + NTHREADS, make_float4(aB.x*inv, aB.y*inv, aB.z*inv, aB.w*inv));

        mA = nA;
        mB = nB;
        // No trailing barrier: buffer r&1 is only rewritten at r+2, and the
        // r+1 barrier separates any straggler reads from that write.
    }
}

extern "C" void kernel_launch(void* const* d_in, const int* in_sizes, int n_in,
                              void* d_out, int out_size)
{
    const float*  coords = (const float*)d_in[0];   // [8,2048,3]
    const float4* masks  = (const float4*)d_in[1];  // [8,2048,2048]
    const float*  sigma  = (const float*)d_in[2];   // [1]
    float4*       out    = (float4*)d_out;          // [8,2048,2048]

    (void)in_sizes; (void)n_in; (void)out_size;

    dim3 grid(NB * NN / RPB);   // 2048 blocks
    dim3 block(NTHREADS);
    gauss_adj_kernel<<<grid, block>>>(coords, masks, sigma, out);
}